// round 12
// baseline (speedup 1.0000x reference)
#include <cuda_runtime.h>
#include <float.h>

// And_Convolution: out[n][s] = min_{k<16} ( in[n][4*s + k] * w[k] )
// N=1024, L=8192, KERNEL=16, STRIDE=4 -> OUTW = (L-16)/4 + 1 = 2045
//
// Decomposition: window s covers float4 indices u = s+d (d=0..3):
//   g_d(u) = min_c in4[u].c * w[4d+c];  out[s] = min_d g_d(s+d)
//
// Round-12: best-cold structure (R8: GROUPS=4, TPB=256, packed f32x2,
// source-side-select single-shuffle assembly) + predicated halo load.
// The halo vector v[GROUPS] is only ever consumed via lanes 0-2 (the
// select t_d = (lane<d) ? g_d[G] : g_d[i] routes halo partials out of
// lanes < d <= 3 only). Loading it in all 32 lanes wasted 4 L1 sectors
// per warp-tile; @lane<3 costs 1 sector. Input wavefronts/L2 sectors:
// 17 -> 13.25 per 128 outputs (-19%).

#define ROW_L4   2048
#define OUTW     2045
#define TPB      256
#define GROUPS   4
#define WARP_OUT (32 * GROUPS)            // 128 outputs per warp
#define CTA_OUT  ((TPB / 32) * WARP_OUT)  // 1024 outputs per CTA
#define CTAS_PER_ROW 2

typedef unsigned long long u64;

__device__ __forceinline__ u64 pk2(float a, float b) {
    u64 r; asm("mov.b64 %0, {%1, %2};" : "=l"(r) : "f"(a), "f"(b)); return r;
}
__device__ __forceinline__ u64 mul2(u64 a, u64 b) {
    u64 r; asm("mul.rn.f32x2 %0, %1, %2;" : "=l"(r) : "l"(a), "l"(b)); return r;
}
__device__ __forceinline__ float2 upk2(u64 p) {
    float x, y; asm("mov.b64 {%0, %1}, %2;" : "=f"(x), "=f"(y) : "l"(p));
    return make_float2(x, y);
}
// min over 4 components of v*w, v/w pre-packed as (lo=xy, hi=zw)
__device__ __forceinline__ float min4w_p(u64 vlo, u64 vhi, u64 wlo, u64 whi) {
    float2 a = upk2(mul2(vlo, wlo));
    float2 b = upk2(mul2(vhi, whi));
    return fminf(fminf(a.x, b.x), fminf(a.y, b.y));
}

__global__ __launch_bounds__(TPB, 5)
void and_conv_kernel(const float4* __restrict__ in,
                     const float*  __restrict__ w,
                     float*        __restrict__ out)
{
    const int row   = blockIdx.x >> 1;
    const int chunk = blockIdx.x & 1;
    const int warp  = threadIdx.x >> 5;
    const int lane  = threadIdx.x & 31;
    const int wbase = chunk * CTA_OUT + warp * WARP_OUT;  // first output/float4

    const float4* __restrict__ rowp = in + (size_t)row * ROW_L4;

    // ---- Phase 1: loads back-to-back (coalesced; halo in lanes 0-2 only) ----
    float4 v[GROUPS + 1];
#pragma unroll
    for (int i = 0; i < GROUPS; ++i)
        v[i] = __ldg(&rowp[wbase + 32 * i + lane]);       // always in-bounds
    v[GROUPS] = make_float4(0.f, 0.f, 0.f, 0.f);
    if (lane < 3) {                                       // only lanes 0-2 used
        int idx = wbase + 32 * GROUPS + lane;             // clamp at row end
        v[GROUPS] = __ldg(&rowp[idx < ROW_L4 - 1 ? idx : ROW_L4 - 1]);
    }

    // Weights, packed into f32x2 pairs (uniform -> broadcast, reg-resident)
    const float4* __restrict__ w4 = reinterpret_cast<const float4*>(w);
    u64 wlo[4], whi[4];
#pragma unroll
    for (int d = 0; d < 4; ++d) {
        float4 wd = __ldg(&w4[d]);
        wlo[d] = pk2(wd.x, wd.y);
        whi[d] = pk2(wd.z, wd.w);
    }

    // ---- Phase 2: partial mins (packed multiplies) ----
    float g0[GROUPS], g1[GROUPS + 1], g2[GROUPS + 1], g3[GROUPS + 1];
#pragma unroll
    for (int i = 0; i <= GROUPS; ++i) {
        const u64 vlo = pk2(v[i].x, v[i].y);   // free: LDG.128 lands pairs
        const u64 vhi = pk2(v[i].z, v[i].w);
        if (i < GROUPS) g0[i] = min4w_p(vlo, vhi, wlo[0], whi[0]);
        g1[i] = min4w_p(vlo, vhi, wlo[1], whi[1]);
        g2[i] = min4w_p(vlo, vhi, wlo[2], whi[2]);
        g3[i] = min4w_p(vlo, vhi, wlo[3], whi[3]);
    }

    // ---- Phase 3: assemble via 3 shuffles per group ----
    const unsigned F = 0xFFFFFFFFu;
    float* __restrict__ orow = out + (size_t)row * OUTW;
#pragma unroll
    for (int i = 0; i < GROUPS; ++i) {
        // Wrapped readers (dest lane >= 32-d) hit src lanes 0..d-1, which
        // must supply group i+1's partial -> source-side select. Only
        // lanes 0-2 ever export halo-derived values, so the lane>=3
        // halo garbage never propagates.
        float t1 = (lane < 1) ? g1[i + 1] : g1[i];
        float t2 = (lane < 2) ? g2[i + 1] : g2[i];
        float t3 = (lane < 3) ? g3[i + 1] : g3[i];
        float n1 = __shfl_sync(F, t1, (lane + 1) & 31);
        float n2 = __shfl_sync(F, t2, (lane + 2) & 31);
        float n3 = __shfl_sync(F, t3, (lane + 3) & 31);

        float r = fminf(fminf(g0[i], n1), fminf(n2, n3));

        int s = wbase + 32 * i + lane;
        if (s < OUTW) orow[s] = r;
    }
}

extern "C" void kernel_launch(void* const* d_in, const int* in_sizes, int n_in,
                              void* d_out, int out_size)
{
    const float* inp = (const float*)d_in[0];   // (N, 8192) fp32
    const float* w   = (const float*)d_in[1];   // (1, 16)   fp32

    const int N = in_sizes[0] / 8192;           // 1024

    and_conv_kernel<<<N * CTAS_PER_ROW, TPB>>>(
        reinterpret_cast<const float4*>(inp), w, (float*)d_out);
}

// round 13
// speedup vs baseline: 1.2251x; 1.2251x over previous
#include <cuda_runtime.h>
#include <float.h>

// And_Convolution: out[n][s] = min_{k<16} ( in[n][4*s + k] * w[k] )
// N=1024, L=8192, KERNEL=16, STRIDE=4 -> OUTW = (L-16)/4 + 1 = 2045
//
// Decomposition: window s covers float4 indices u = s+d (d=0..3):
//   g_d(u) = min_c in4[u].c * w[4d+c];  out[s] = min_d g_d(s+d)
//
// Round-13: best-timed structure (R7: TPB=128, GROUPS=8, packed
// mul.rn.f32x2, source-side-select single-shuffle assembly; timed 8.64us)
// + predicated halo load. v[GROUPS] is only consumed via lanes 0-2 (the
// select t_d = (lane<d)? g_d[G] : g_d[i] exports halo partials from lanes
// < d <= 3 only), so the halo LDG runs at lane<3: one L1 sector instead
// of four, and one fewer full-width load in the front batch.

#define ROW_L4   2048
#define OUTW     2045
#define TPB      128
#define GROUPS   8
#define WARP_OUT (32 * GROUPS)            // 256 outputs per warp
#define CTA_OUT  ((TPB / 32) * WARP_OUT)  // 1024 outputs per CTA
#define CTAS_PER_ROW 2

typedef unsigned long long u64;

__device__ __forceinline__ u64 pk2(float a, float b) {
    u64 r; asm("mov.b64 %0, {%1, %2};" : "=l"(r) : "f"(a), "f"(b)); return r;
}
__device__ __forceinline__ u64 mul2(u64 a, u64 b) {
    u64 r; asm("mul.rn.f32x2 %0, %1, %2;" : "=l"(r) : "l"(a), "l"(b)); return r;
}
__device__ __forceinline__ float2 upk2(u64 p) {
    float x, y; asm("mov.b64 {%0, %1}, %2;" : "=f"(x), "=f"(y) : "l"(p));
    return make_float2(x, y);
}
// min over 4 components of v*w, v/w pre-packed as (lo=xy, hi=zw)
__device__ __forceinline__ float min4w_p(u64 vlo, u64 vhi, u64 wlo, u64 whi) {
    float2 a = upk2(mul2(vlo, wlo));
    float2 b = upk2(mul2(vhi, whi));
    return fminf(fminf(a.x, b.x), fminf(a.y, b.y));
}

__global__ __launch_bounds__(TPB)
void and_conv_kernel(const float4* __restrict__ in,
                     const float*  __restrict__ w,
                     float*        __restrict__ out)
{
    const int row   = blockIdx.x >> 1;
    const int chunk = blockIdx.x & 1;
    const int warp  = threadIdx.x >> 5;
    const int lane  = threadIdx.x & 31;
    const int wbase = chunk * CTA_OUT + warp * WARP_OUT;  // first output/float4

    const float4* __restrict__ rowp = in + (size_t)row * ROW_L4;

    // ---- Phase 1: loads back-to-back (MLP=8 full + 1 partial, coalesced) ----
    float4 v[GROUPS + 1];
#pragma unroll
    for (int i = 0; i < GROUPS; ++i)
        v[i] = __ldg(&rowp[wbase + 32 * i + lane]);       // always in-bounds
    v[GROUPS] = make_float4(0.f, 0.f, 0.f, 0.f);
    if (lane < 3) {                                       // only lanes 0-2 used
        int idx = wbase + 32 * GROUPS + lane;             // clamp at row end
        v[GROUPS] = __ldg(&rowp[idx < ROW_L4 - 1 ? idx : ROW_L4 - 1]);
    }

    // Weights, packed into f32x2 pairs (uniform -> broadcast, reg-resident)
    const float4* __restrict__ w4 = reinterpret_cast<const float4*>(w);
    u64 wlo[4], whi[4];
#pragma unroll
    for (int d = 0; d < 4; ++d) {
        float4 wd = __ldg(&w4[d]);
        wlo[d] = pk2(wd.x, wd.y);
        whi[d] = pk2(wd.z, wd.w);
    }

    // ---- Phase 2: partial mins (packed multiplies) ----
    float g0[GROUPS], g1[GROUPS + 1], g2[GROUPS + 1], g3[GROUPS + 1];
#pragma unroll
    for (int i = 0; i <= GROUPS; ++i) {
        const u64 vlo = pk2(v[i].x, v[i].y);   // free: LDG.128 lands pairs
        const u64 vhi = pk2(v[i].z, v[i].w);
        if (i < GROUPS) g0[i] = min4w_p(vlo, vhi, wlo[0], whi[0]);
        g1[i] = min4w_p(vlo, vhi, wlo[1], whi[1]);
        g2[i] = min4w_p(vlo, vhi, wlo[2], whi[2]);
        g3[i] = min4w_p(vlo, vhi, wlo[3], whi[3]);
    }

    // ---- Phase 3: assemble via 3 shuffles per group ----
    const unsigned F = 0xFFFFFFFFu;
    float* __restrict__ orow = out + (size_t)row * OUTW;
#pragma unroll
    for (int i = 0; i < GROUPS; ++i) {
        // Wrapped readers (dest lane >= 32-d) hit src lanes 0..d-1, which
        // must supply group i+1's partial -> source-side select. Only
        // lanes 0-2 ever export halo-derived values, so lane>=3 halo
        // zeros never propagate.
        float t1 = (lane < 1) ? g1[i + 1] : g1[i];
        float t2 = (lane < 2) ? g2[i + 1] : g2[i];
        float t3 = (lane < 3) ? g3[i + 1] : g3[i];
        float n1 = __shfl_sync(F, t1, (lane + 1) & 31);
        float n2 = __shfl_sync(F, t2, (lane + 2) & 31);
        float n3 = __shfl_sync(F, t3, (lane + 3) & 31);

        float r = fminf(fminf(g0[i], n1), fminf(n2, n3));

        int s = wbase + 32 * i + lane;
        if (s < OUTW) orow[s] = r;
    }
}

extern "C" void kernel_launch(void* const* d_in, const int* in_sizes, int n_in,
                              void* d_out, int out_size)
{
    const float* inp = (const float*)d_in[0];   // (N, 8192) fp32
    const float* w   = (const float*)d_in[1];   // (1, 16)   fp32

    const int N = in_sizes[0] / 8192;           // 1024

    and_conv_kernel<<<N * CTAS_PER_ROW, TPB>>>(
        reinterpret_cast<const float4*>(inp), w, (float*)d_out);
}